// round 16
// baseline (speedup 1.0000x reference)
#include <cuda_runtime.h>

// Spline1DInterpolant: out[q] = sum_i c[i] * u(|s_q + 2 - (i+1)|),
// s = (x - a)/h, h = (b - a)/n. Cubic B-spline, support t < 2 => exactly 4
// consecutive taps: i = floor(s) .. floor(s)+3.
//
// Overhead-bound (all pipes <3%). Bench-best shape: vec4 queries/thread,
// 128 single-warp blocks, direct gathers, NO prefetch/smem (both measurably
// regress the warm bench). This round: closed-form tap weights.
//   base = s + 2 (ref rounding), t0 = base - (i0+1) is EXACT (same-ulp-grid
//   subtraction), u = t0-1, g = 2-t0 exact => the 4 reference taps are
//   w = { g^3, 4-6u^2+3u^3, 4-6g^2+3g^3, u^3 } with identical t rounding to
//   the reference, at half the instruction count (no per-tap I2F/FABS/SEL,
//   single clamp instead of 4 bounds predicates).

__device__ __forceinline__ float eval_query(float xq, float a0, float h,
                                            const float* __restrict__ c, int nc) {
    float s = (xq - a0) / h;            // reference-exact rounding
    int i0 = (int)floorf(s);
    i0 = max(0, min(i0, nc - 4));       // memory safety; identity for x in [a,b)

    float base = s + 2.0f;              // reference's rounded (s + 2)
    float t0 = base - ((float)i0 + 1.0f);   // exact; in [1,2)
    float u  = t0 - 1.0f;               // exact; = frac(s) with ref rounding
    float g  = 2.0f - t0;               // exact; = 1 - u

    float u2 = u * u, g2 = g * g;
    float u3 = u2 * u, g3 = g2 * g;
    float w1 = fmaf(3.0f, u3, fmaf(-6.0f, u2, 4.0f));
    float w2 = fmaf(3.0f, g3, fmaf(-6.0f, g2, 4.0f));

    float sum = __ldg(c + i0) * g3;               // ascending i, like reference
    sum = fmaf(__ldg(c + i0 + 1), w1, sum);
    sum = fmaf(__ldg(c + i0 + 2), w2, sum);
    sum = fmaf(__ldg(c + i0 + 3), u3, sum);
    return sum;
}

__global__ void __launch_bounds__(32)
spline1d_vec4(const float4* __restrict__ x4,
              const float* __restrict__ a,
              const float* __restrict__ b,
              const float* __restrict__ n,
              const float* __restrict__ c,
              float4* __restrict__ out4,
              int nb4, int nc) {
    int tid = blockIdx.x * 32 + threadIdx.x;
    if (tid >= nb4) return;

    // Independent loads issue together: x vector + broadcast scalars.
    float4 xv = __ldg(x4 + tid);
    float a0 = __ldg(a);
    float h  = (__ldg(b) - a0) / __ldg(n);

    float4 r;
    r.x = eval_query(xv.x, a0, h, c, nc);
    r.y = eval_query(xv.y, a0, h, c, nc);
    r.z = eval_query(xv.z, a0, h, c, nc);
    r.w = eval_query(xv.w, a0, h, c, nc);

    out4[tid] = r;
}

// Scalar tail (only if nb % 4 != 0; never for the fixed B=16384 shape).
__global__ void __launch_bounds__(32)
spline1d_tail(const float* __restrict__ x,
              const float* __restrict__ a,
              const float* __restrict__ b,
              const float* __restrict__ n,
              const float* __restrict__ c,
              float* __restrict__ out,
              int start, int nb, int nc) {
    int tid = start + blockIdx.x * 32 + threadIdx.x;
    if (tid >= nb) return;
    float a0 = __ldg(a);
    float h  = (__ldg(b) - a0) / __ldg(n);
    out[tid] = eval_query(__ldg(x + tid), a0, h, c, nc);
}

extern "C" void kernel_launch(void* const* d_in, const int* in_sizes, int n_in,
                              void* d_out, int out_size) {
    const float* x = (const float*)d_in[0];   // [B,1] fp32
    const float* a = (const float*)d_in[1];   // [1]
    const float* b = (const float*)d_in[2];   // [1]
    const float* n = (const float*)d_in[3];   // [1]
    const float* c = (const float*)d_in[4];   // [C]
    float* out = (float*)d_out;

    int nb = in_sizes[0];      // 16384
    int nc = in_sizes[4];      // 4096

    int nb4 = nb >> 2;
    if (nb4 > 0) {
        int blocks = (nb4 + 31) / 32;          // 128 single-warp blocks
        spline1d_vec4<<<blocks, 32>>>((const float4*)x, a, b, n, c,
                                      (float4*)out, nb4, nc);
    }
    int rem = nb & 3;
    if (rem) {
        spline1d_tail<<<1, 32>>>(x, a, b, n, c, out, nb4 << 2, nb, nc);
    }
}